// round 4
// baseline (speedup 1.0000x reference)
#include <cuda_runtime.h>
#include <cuda_bf16.h>
#include <cstdint>
#include <cstddef>

#define SEQ    4096
#define DMODEL 512
#define NHEAD  8
#define DK     64

// Scratch (static device globals — no allocation in kernel_launch)
__device__ __nv_bfloat16 g_Qhi[2 * SEQ * DMODEL];
__device__ __nv_bfloat16 g_Qlo[2 * SEQ * DMODEL];
__device__ __nv_bfloat16 g_Khi[2 * SEQ * DMODEL];
__device__ __nv_bfloat16 g_Klo[2 * SEQ * DMODEL];
__device__ __nv_bfloat16 g_Vhi[2 * SEQ * DMODEL];
__device__ __nv_bfloat16 g_Vlo[2 * SEQ * DMODEL];
__device__ float         g_C  [2 * SEQ * DMODEL];

// ---------------------------------------------------------------------------
// helpers
// ---------------------------------------------------------------------------
#define SWZ(o) ((o) ^ (((o) >> 3) & 0x70))

__device__ __forceinline__ uint32_t smem_u32(const void* p) {
    uint32_t a;
    asm("{ .reg .u64 t; cvta.to.shared.u64 t, %1; cvt.u32.u64 %0, t; }" : "=r"(a) : "l"(p));
    return a;
}
__device__ __forceinline__ void cpa16(uint32_t dst, const void* src) {
    asm volatile("cp.async.cg.shared.global [%0], [%1], 16;" :: "r"(dst), "l"(src) : "memory");
}
#define CP_COMMIT() asm volatile("cp.async.commit_group;" ::: "memory")
#define CP_WAIT(n)  asm volatile("cp.async.wait_group %0;" :: "n"(n) : "memory")

__device__ __forceinline__ void ldsm_x4(uint32_t* r, uint32_t addr) {
    asm volatile("ldmatrix.sync.aligned.m8n8.x4.shared.b16 {%0,%1,%2,%3}, [%4];"
                 : "=r"(r[0]), "=r"(r[1]), "=r"(r[2]), "=r"(r[3]) : "r"(addr));
}
__device__ __forceinline__ void ldsm_x2(uint32_t& r0, uint32_t& r1, uint32_t addr) {
    asm volatile("ldmatrix.sync.aligned.m8n8.x2.shared.b16 {%0,%1}, [%2];"
                 : "=r"(r0), "=r"(r1) : "r"(addr));
}
__device__ __forceinline__ void ldsm_x2t(uint32_t& r0, uint32_t& r1, uint32_t addr) {
    asm volatile("ldmatrix.sync.aligned.m8n8.x2.trans.shared.b16 {%0,%1}, [%2];"
                 : "=r"(r0), "=r"(r1) : "r"(addr));
}
__device__ __forceinline__ void mma16816(float* c, const uint32_t* a, uint32_t b0, uint32_t b1) {
    asm volatile("mma.sync.aligned.m16n8k16.row.col.f32.bf16.bf16.f32 "
                 "{%0,%1,%2,%3}, {%4,%5,%6,%7}, {%8,%9}, {%0,%1,%2,%3};"
                 : "+f"(c[0]), "+f"(c[1]), "+f"(c[2]), "+f"(c[3])
                 : "r"(a[0]), "r"(a[1]), "r"(a[2]), "r"(a[3]), "r"(b0), "r"(b1));
}
__device__ __forceinline__ void split2(float a, float b, uint32_t& hi, uint32_t& lo) {
    __nv_bfloat162 hp = __floats2bfloat162_rn(a, b);
    float ar = a - __bfloat162float(hp.x);
    float br = b - __bfloat162float(hp.y);
    __nv_bfloat162 lp = __floats2bfloat162_rn(ar, br);
    hi = *reinterpret_cast<uint32_t*>(&hp);
    lo = *reinterpret_cast<uint32_t*>(&lp);
}

// ---------------------------------------------------------------------------
// SMEM: two 32KB tile buffers (KHI/KLO/VHI/VLO 8KB each) + 2 mask bufs.
// Q staging (hi 16KB @0, lo 16KB @16384) reuses buffer 0 before the loop.
// ---------------------------------------------------------------------------
#define BUFSZ  32768u
#define OKLO   8192u
#define OVHI   16384u
#define OVLO   24576u
#define OMSK   65536u
#define SMEM_BYTES (66048u + 1024u)

// ---------------------------------------------------------------------------
// FA2 attention, mma.sync bf16 hi/lo. CTA = 64 q rows (4 warps x 16), 2 CTA/SM.
// Double-buffered cp.async K/V tiles (64 keys).
// ---------------------------------------------------------------------------
__global__ __launch_bounds__(128, 2)
void flash_mma(const __nv_bfloat16* __restrict__ Qhi, const __nv_bfloat16* __restrict__ Qlo,
               const __nv_bfloat16* __restrict__ Khi, const __nv_bfloat16* __restrict__ Klo,
               const __nv_bfloat16* __restrict__ Vhi, const __nv_bfloat16* __restrict__ Vlo,
               const int* __restrict__ mask, float* __restrict__ O)
{
    extern __shared__ char dsm[];
    char* sb = (char*)(((uintptr_t)dsm + 1023) & ~(uintptr_t)1023);
    const uint32_t sbase = smem_u32(sb);

    const int tid  = threadIdx.x;
    const int wid  = tid >> 5;
    const int lane = tid & 31;

    const int b  = blockIdx.y >> 3;
    const int h  = blockIdx.y & 7;
    const int q0 = blockIdx.x * 64;

    const size_t bh_off = (size_t)b * SEQ * DMODEL + h * DK;
    const __nv_bfloat16* Qbh = Qhi + bh_off + (size_t)q0 * DMODEL;
    const __nv_bfloat16* Qbl = Qlo + bh_off + (size_t)q0 * DMODEL;
    const __nv_bfloat16* Kbh = Khi + bh_off;
    const __nv_bfloat16* Kbl = Klo + bh_off;
    const __nv_bfloat16* Vbh = Vhi + bh_off;
    const __nv_bfloat16* Vbl = Vlo + bh_off;
    const int* mb = mask + (size_t)b * SEQ;

    const int row = tid >> 1;
    const int ch0 = (tid & 1) * 4;

    // ---- stage Q (64x64 hi/lo) into buffer0 via cp.async ----
    {
        const __nv_bfloat16* qh_src = Qbh + (size_t)row * DMODEL;
        const __nv_bfloat16* ql_src = Qbl + (size_t)row * DMODEL;
#pragma unroll
        for (int e = 0; e < 4; e++) {
            int ch = ch0 + e;
            uint32_t so = SWZ((uint32_t)row * 128u + (uint32_t)ch * 16u);
            cpa16(sbase + so,          qh_src + ch * 8);
            cpa16(sbase + 16384u + so, ql_src + ch * 8);
        }
        CP_COMMIT();
    }
    CP_WAIT(0);
    __syncthreads();

    // ---- Q fragments ----
    uint32_t qh[4][4], ql[4][4];
    {
        const int r  = wid * 16 + (lane & 15);
        const int cb = (lane >> 4);
#pragma unroll
        for (int ks = 0; ks < 4; ks++) {
            uint32_t off = SWZ((uint32_t)r * 128u + (uint32_t)(ks * 2 + cb) * 16u);
            ldsm_x4(qh[ks], sbase + off);
            ldsm_x4(ql[ks], sbase + 16384u + off);
        }
    }
    __syncthreads();

    // ---- prologue: prefetch tile 0 into buffer 0 ----
    {
        size_t ro = (size_t)row * DMODEL;
#pragma unroll
        for (int e = 0; e < 4; e++) {
            int ch = ch0 + e;
            uint32_t so = SWZ((uint32_t)row * 128u + (uint32_t)ch * 16u);
            cpa16(sbase + so,        Kbh + ro + ch * 8);
            cpa16(sbase + OKLO + so, Kbl + ro + ch * 8);
            cpa16(sbase + OVHI + so, Vbh + ro + ch * 8);
            cpa16(sbase + OVLO + so, Vbl + ro + ch * 8);
        }
        CP_COMMIT();
        if (tid < 64) ((float*)(sb + OMSK))[tid] = (mb[tid] == 0) ? -1e9f : 0.f;
    }

    float o[8][4];
#pragma unroll
    for (int nb = 0; nb < 8; nb++)
#pragma unroll
        for (int j = 0; j < 4; j++) o[nb][j] = 0.f;
    float m0 = -1e30f, m1 = -1e30f, l0 = 0.f, l1 = 0.f;

    const int nT = SEQ / 64;
    for (int t = 0; t < nT; t++) {
        const uint32_t p  = (uint32_t)(t & 1);
        const uint32_t bb = sbase + p * BUFSZ;
        float* mskp = (float*)(sb + OMSK + p * 256u);

        // prefetch tile t+1 into other buffer
        if (t + 1 < nT) {
            size_t ro = (size_t)((t + 1) * 64 + row) * DMODEL;
            uint32_t ob = sbase + (p ^ 1u) * BUFSZ;
#pragma unroll
            for (int e = 0; e < 4; e++) {
                int ch = ch0 + e;
                uint32_t so = SWZ((uint32_t)row * 128u + (uint32_t)ch * 16u);
                cpa16(ob + so,        Kbh + ro + ch * 8);
                cpa16(ob + OKLO + so, Kbl + ro + ch * 8);
                cpa16(ob + OVHI + so, Vbh + ro + ch * 8);
                cpa16(ob + OVLO + so, Vbl + ro + ch * 8);
            }
            if (tid < 64)
                ((float*)(sb + OMSK + (p ^ 1u) * 256u))[tid] =
                    (mb[(t + 1) * 64 + tid] == 0) ? -1e9f : 0.f;
        }
        CP_COMMIT();
        CP_WAIT(1);
        __syncthreads();   // tile t data + mask visible to all warps

        // ---- S = Q K^T (HH + LH + HL) ----
        float s[8][4];
#pragma unroll
        for (int nb = 0; nb < 8; nb++) {
#pragma unroll
            for (int j = 0; j < 4; j++) s[nb][j] = 0.f;
#pragma unroll
            for (int ks = 0; ks < 4; ks++) {
                const int krow = nb * 8 + (lane & 7);
                const int kch  = ks * 2 + ((lane >> 3) & 1);
                uint32_t off = SWZ((uint32_t)krow * 128u + (uint32_t)kch * 16u);
                uint32_t bh0, bh1, bl0, bl1;
                ldsm_x2(bh0, bh1, bb + off);
                ldsm_x2(bl0, bl1, bb + OKLO + off);
                mma16816(s[nb], qh[ks], bh0, bh1);
                mma16816(s[nb], ql[ks], bh0, bh1);
                mma16816(s[nb], qh[ks], bl0, bl1);
            }
        }

        // ---- online softmax ----
        float rm0 = -1e30f, rm1 = -1e30f;
#pragma unroll
        for (int nb = 0; nb < 8; nb++) {
            float2 mk = *(const float2*)(mskp + nb * 8 + (lane & 3) * 2);
            s[nb][0] = s[nb][0] * 0.125f + mk.x;
            s[nb][1] = s[nb][1] * 0.125f + mk.y;
            s[nb][2] = s[nb][2] * 0.125f + mk.x;
            s[nb][3] = s[nb][3] * 0.125f + mk.y;
            rm0 = fmaxf(rm0, fmaxf(s[nb][0], s[nb][1]));
            rm1 = fmaxf(rm1, fmaxf(s[nb][2], s[nb][3]));
        }
        rm0 = fmaxf(rm0, __shfl_xor_sync(0xffffffffu, rm0, 1));
        rm0 = fmaxf(rm0, __shfl_xor_sync(0xffffffffu, rm0, 2));
        rm1 = fmaxf(rm1, __shfl_xor_sync(0xffffffffu, rm1, 1));
        rm1 = fmaxf(rm1, __shfl_xor_sync(0xffffffffu, rm1, 2));

        const float mn0 = fmaxf(m0, rm0), mn1 = fmaxf(m1, rm1);
        const float a0 = __expf(m0 - mn0), a1 = __expf(m1 - mn1);
        m0 = mn0; m1 = mn1;

        float rs0 = 0.f, rs1 = 0.f;
#pragma unroll
        for (int nb = 0; nb < 8; nb++) {
            s[nb][0] = __expf(s[nb][0] - mn0);
            s[nb][1] = __expf(s[nb][1] - mn0);
            s[nb][2] = __expf(s[nb][2] - mn1);
            s[nb][3] = __expf(s[nb][3] - mn1);
            rs0 += s[nb][0] + s[nb][1];
            rs1 += s[nb][2] + s[nb][3];
        }
        rs0 += __shfl_xor_sync(0xffffffffu, rs0, 1);
        rs0 += __shfl_xor_sync(0xffffffffu, rs0, 2);
        rs1 += __shfl_xor_sync(0xffffffffu, rs1, 1);
        rs1 += __shfl_xor_sync(0xffffffffu, rs1, 2);
        l0 = l0 * a0 + rs0;
        l1 = l1 * a1 + rs1;

#pragma unroll
        for (int nb = 0; nb < 8; nb++) {
            o[nb][0] *= a0; o[nb][1] *= a0;
            o[nb][2] *= a1; o[nb][3] *= a1;
        }

        // ---- P -> bf16 hi/lo fragments ----
        uint32_t ph[8][2], pl[8][2];
#pragma unroll
        for (int nb = 0; nb < 8; nb++) {
            split2(s[nb][0], s[nb][1], ph[nb][0], pl[nb][0]);
            split2(s[nb][2], s[nb][3], ph[nb][1], pl[nb][1]);
        }

        // ---- O += P V ----
#pragma unroll
        for (int nb = 0; nb < 8; nb++) {
#pragma unroll
            for (int ks = 0; ks < 4; ks++) {
                const int vrow = ks * 16 + (lane & 15);
                uint32_t off = SWZ((uint32_t)vrow * 128u + (uint32_t)nb * 16u);
                uint32_t vh0, vh1, vl0, vl1;
                ldsm_x2t(vh0, vh1, bb + OVHI + off);
                ldsm_x2t(vl0, vl1, bb + OVLO + off);
                uint32_t ah[4] = {ph[2 * ks][0], ph[2 * ks][1], ph[2 * ks + 1][0], ph[2 * ks + 1][1]};
                uint32_t al[4] = {pl[2 * ks][0], pl[2 * ks][1], pl[2 * ks + 1][0], pl[2 * ks + 1][1]};
                mma16816(o[nb], ah, vh0, vh1);
                mma16816(o[nb], al, vh0, vh1);
                mma16816(o[nb], ah, vl0, vl1);
            }
        }
        __syncthreads();   // all warps done with buffer p before it is refilled
    }

    // ---- epilogue ----
    const float i0 = 1.f / l0, i1 = 1.f / l1;
    const int r  = lane >> 2;
    const int cb = (lane & 3) * 2;
    float* Ob = O + ((size_t)b * SEQ + q0 + wid * 16) * DMODEL + h * DK;
#pragma unroll
    for (int nb = 0; nb < 8; nb++) {
        float2 v0 = make_float2(o[nb][0] * i0, o[nb][1] * i0);
        float2 v1 = make_float2(o[nb][2] * i1, o[nb][3] * i1);
        *(float2*)(Ob + (size_t)r * DMODEL + nb * 8 + cb)       = v0;
        *(float2*)(Ob + (size_t)(r + 8) * DMODEL + nb * 8 + cb) = v1;
    }
}

// ---------------------------------------------------------------------------
// fp32 GEMM (C = A @ W^T + b), epilogue writes bf16 hi/lo arrays
// ---------------------------------------------------------------------------
__global__ __launch_bounds__(256)
void gemm_bias_split(const float* __restrict__ A, const float* __restrict__ W,
                     const float* __restrict__ bias,
                     __nv_bfloat16* __restrict__ Chi, __nv_bfloat16* __restrict__ Clo,
                     int M, int N, int K)
{
    __shared__ float As[16][128];
    __shared__ float Ws[16][128];

    const int tid  = threadIdx.x;
    const int brow = blockIdx.y * 128;
    const int bcol = blockIdx.x * 128;
    const int tr   = (tid / 16) * 8;
    const int tc   = (tid % 16) * 8;
    const int lr   = tid / 4;
    const int lc   = (tid % 4) * 4;

    float acc[8][8];
#pragma unroll
    for (int i = 0; i < 8; i++)
#pragma unroll
        for (int j = 0; j < 8; j++) acc[i][j] = 0.f;

    for (int k0 = 0; k0 < K; k0 += 16) {
#pragma unroll
        for (int i = 0; i < 2; i++) {
            int r = lr + i * 64;
            float4 va = *reinterpret_cast<const float4*>(A + (size_t)(brow + r) * K + k0 + lc);
            As[lc + 0][r] = va.x; As[lc + 1][r] = va.y;
            As[lc + 2][r] = va.z; As[lc + 3][r] = va.w;
            float4 vw = *reinterpret_cast<const float4*>(W + (size_t)(bcol + r) * K + k0 + lc);
            Ws[lc + 0][r] = vw.x; Ws[lc + 1][r] = vw.y;
            Ws[lc + 2][r] = vw.z; Ws[lc + 3][r] = vw.w;
        }
        __syncthreads();
#pragma unroll
        for (int k = 0; k < 16; k++) {
            float4 a0 = *reinterpret_cast<const float4*>(&As[k][tr]);
            float4 a1 = *reinterpret_cast<const float4*>(&As[k][tr + 4]);
            float4 b0 = *reinterpret_cast<const float4*>(&Ws[k][tc]);
            float4 b1 = *reinterpret_cast<const float4*>(&Ws[k][tc + 4]);
            float a[8] = {a0.x, a0.y, a0.z, a0.w, a1.x, a1.y, a1.z, a1.w};
            float b[8] = {b0.x, b0.y, b0.z, b0.w, b1.x, b1.y, b1.z, b1.w};
#pragma unroll
            for (int i = 0; i < 8; i++)
#pragma unroll
                for (int j = 0; j < 8; j++)
                    acc[i][j] += a[i] * b[j];
        }
        __syncthreads();
    }

    float4 bv0 = *reinterpret_cast<const float4*>(bias + bcol + tc);
    float4 bv1 = *reinterpret_cast<const float4*>(bias + bcol + tc + 4);
    float bb[8] = {bv0.x, bv0.y, bv0.z, bv0.w, bv1.x, bv1.y, bv1.z, bv1.w};
#pragma unroll
    for (int i = 0; i < 8; i++) {
        uint32_t hv[4], lv[4];
#pragma unroll
        for (int e = 0; e < 4; e++)
            split2(acc[i][2 * e] + bb[2 * e], acc[i][2 * e + 1] + bb[2 * e + 1], hv[e], lv[e]);
        size_t off = (size_t)(brow + tr + i) * N + bcol + tc;
        *reinterpret_cast<uint4*>(Chi + off) = make_uint4(hv[0], hv[1], hv[2], hv[3]);
        *reinterpret_cast<uint4*>(Clo + off) = make_uint4(lv[0], lv[1], lv[2], lv[3]);
    }
}

// ---------------------------------------------------------------------------
// fp32 GEMM with fp32 output (O projection)
// ---------------------------------------------------------------------------
__global__ __launch_bounds__(256)
void gemm_bias_kernel(const float* __restrict__ A, const float* __restrict__ W,
                      const float* __restrict__ bias, float* __restrict__ C,
                      int M, int N, int K)
{
    __shared__ float As[16][128];
    __shared__ float Ws[16][128];

    const int tid  = threadIdx.x;
    const int brow = blockIdx.y * 128;
    const int bcol = blockIdx.x * 128;
    const int tr   = (tid / 16) * 8;
    const int tc   = (tid % 16) * 8;
    const int lr   = tid / 4;
    const int lc   = (tid % 4) * 4;

    float acc[8][8];
#pragma unroll
    for (int i = 0; i < 8; i++)
#pragma unroll
        for (int j = 0; j < 8; j++) acc[i][j] = 0.f;

    for (int k0 = 0; k0 < K; k0 += 16) {
#pragma unroll
        for (int i = 0; i < 2; i++) {
            int r = lr + i * 64;
            float4 va = *reinterpret_cast<const float4*>(A + (size_t)(brow + r) * K + k0 + lc);
            As[lc + 0][r] = va.x; As[lc + 1][r] = va.y;
            As[lc + 2][r] = va.z; As[lc + 3][r] = va.w;
            float4 vw = *reinterpret_cast<const float4*>(W + (size_t)(bcol + r) * K + k0 + lc);
            Ws[lc + 0][r] = vw.x; Ws[lc + 1][r] = vw.y;
            Ws[lc + 2][r] = vw.z; Ws[lc + 3][r] = vw.w;
        }
        __syncthreads();
#pragma unroll
        for (int k = 0; k < 16; k++) {
            float4 a0 = *reinterpret_cast<const float4*>(&As[k][tr]);
            float4 a1 = *reinterpret_cast<const float4*>(&As[k][tr + 4]);
            float4 b0 = *reinterpret_cast<const float4*>(&Ws[k][tc]);
            float4 b1 = *reinterpret_cast<const float4*>(&Ws[k][tc + 4]);
            float a[8] = {a0.x, a0.y, a0.z, a0.w, a1.x, a1.y, a1.z, a1.w};
            float b[8] = {b0.x, b0.y, b0.z, b0.w, b1.x, b1.y, b1.z, b1.w};
#pragma unroll
            for (int i = 0; i < 8; i++)
#pragma unroll
                for (int j = 0; j < 8; j++)
                    acc[i][j] += a[i] * b[j];
        }
        __syncthreads();
    }

    float4 bv0 = *reinterpret_cast<const float4*>(bias + bcol + tc);
    float4 bv1 = *reinterpret_cast<const float4*>(bias + bcol + tc + 4);
    float bb[8] = {bv0.x, bv0.y, bv0.z, bv0.w, bv1.x, bv1.y, bv1.z, bv1.w};
#pragma unroll
    for (int i = 0; i < 8; i++) {
        float4 o0 = make_float4(acc[i][0] + bb[0], acc[i][1] + bb[1],
                                acc[i][2] + bb[2], acc[i][3] + bb[3]);
        float4 o1 = make_float4(acc[i][4] + bb[4], acc[i][5] + bb[5],
                                acc[i][6] + bb[6], acc[i][7] + bb[7]);
        float* crow = C + (size_t)(brow + tr + i) * N + bcol + tc;
        *reinterpret_cast<float4*>(crow)     = o0;
        *reinterpret_cast<float4*>(crow + 4) = o1;
    }
}

// ---------------------------------------------------------------------------
extern "C" void kernel_launch(void* const* d_in, const int* in_sizes, int n_in,
                              void* d_out, int out_size)
{
    const float* q    = (const float*)d_in[0];
    const float* k    = (const float*)d_in[1];
    const float* v    = (const float*)d_in[2];
    const int*   mask = (const int*)  d_in[3];
    const float* Wq   = (const float*)d_in[4];
    const float* bq   = (const float*)d_in[5];
    const float* Wk   = (const float*)d_in[6];
    const float* bk   = (const float*)d_in[7];
    const float* Wv   = (const float*)d_in[8];
    const float* bv   = (const float*)d_in[9];
    const float* Wo   = (const float*)d_in[10];
    const float* bo   = (const float*)d_in[11];

    const int S = SEQ, D = DMODEL;
    const int B = in_sizes[0] / (S * D);
    const int M = B * S;

    __nv_bfloat16 *gQh, *gQl, *gKh, *gKl, *gVh, *gVl;
    float* gC;
    cudaGetSymbolAddress((void**)&gQh, g_Qhi);
    cudaGetSymbolAddress((void**)&gQl, g_Qlo);
    cudaGetSymbolAddress((void**)&gKh, g_Khi);
    cudaGetSymbolAddress((void**)&gKl, g_Klo);
    cudaGetSymbolAddress((void**)&gVh, g_Vhi);
    cudaGetSymbolAddress((void**)&gVl, g_Vlo);
    cudaGetSymbolAddress((void**)&gC,  g_C);

    dim3 ggrid(D / 128, M / 128);
    gemm_bias_split<<<ggrid, 256>>>(q, Wq, bq, gQh, gQl, M, D, D);
    gemm_bias_split<<<ggrid, 256>>>(k, Wk, bk, gKh, gKl, M, D, D);
    gemm_bias_split<<<ggrid, 256>>>(v, Wv, bv, gVh, gVl, M, D, D);

    cudaFuncSetAttribute(flash_mma, cudaFuncAttributeMaxDynamicSharedMemorySize, SMEM_BYTES);
    flash_mma<<<dim3(S / 64, B * NHEAD), 128, SMEM_BYTES>>>(gQh, gQl, gKh, gKl, gVh, gVl, mask, gC);

    gemm_bias_kernel<<<ggrid, 256>>>(gC, Wo, bo, (float*)d_out, M, D, D);
}

// round 5
// speedup vs baseline: 1.6044x; 1.6044x over previous
#include <cuda_runtime.h>
#include <cuda_bf16.h>
#include <cstdint>
#include <cstddef>

#define SEQ    4096
#define DMODEL 512
#define NHEAD  8
#define DK     64

// Scratch (static device globals — no allocation in kernel_launch)
__device__ __nv_bfloat16 g_Qhi[2 * SEQ * DMODEL];
__device__ __nv_bfloat16 g_Qlo[2 * SEQ * DMODEL];
__device__ __nv_bfloat16 g_Khi[2 * SEQ * DMODEL];
__device__ __nv_bfloat16 g_Klo[2 * SEQ * DMODEL];
__device__ __nv_bfloat16 g_Vhi[2 * SEQ * DMODEL];
__device__ __nv_bfloat16 g_Vlo[2 * SEQ * DMODEL];
__device__ float         g_C  [2 * SEQ * DMODEL];

// ---------------------------------------------------------------------------
// helpers
// ---------------------------------------------------------------------------
#define SWZ(o) ((o) ^ (((o) >> 3) & 0x70))

__device__ __forceinline__ uint32_t smem_u32(const void* p) {
    uint32_t a;
    asm("{ .reg .u64 t; cvta.to.shared.u64 t, %1; cvt.u32.u64 %0, t; }" : "=r"(a) : "l"(p));
    return a;
}
__device__ __forceinline__ void cpa16(uint32_t dst, const void* src) {
    asm volatile("cp.async.cg.shared.global [%0], [%1], 16;" :: "r"(dst), "l"(src) : "memory");
}
#define CP_COMMIT() asm volatile("cp.async.commit_group;" ::: "memory")
#define CP_WAIT(n)  asm volatile("cp.async.wait_group %0;" :: "n"(n) : "memory")

__device__ __forceinline__ void ldsm_x4(uint32_t* r, uint32_t addr) {
    asm volatile("ldmatrix.sync.aligned.m8n8.x4.shared.b16 {%0,%1,%2,%3}, [%4];"
                 : "=r"(r[0]), "=r"(r[1]), "=r"(r[2]), "=r"(r[3]) : "r"(addr));
}
__device__ __forceinline__ void ldsm_x2(uint32_t& r0, uint32_t& r1, uint32_t addr) {
    asm volatile("ldmatrix.sync.aligned.m8n8.x2.shared.b16 {%0,%1}, [%2];"
                 : "=r"(r0), "=r"(r1) : "r"(addr));
}
__device__ __forceinline__ void ldsm_x2t(uint32_t& r0, uint32_t& r1, uint32_t addr) {
    asm volatile("ldmatrix.sync.aligned.m8n8.x2.trans.shared.b16 {%0,%1}, [%2];"
                 : "=r"(r0), "=r"(r1) : "r"(addr));
}
__device__ __forceinline__ void mma16816(float* c, const uint32_t* a, uint32_t b0, uint32_t b1) {
    asm volatile("mma.sync.aligned.m16n8k16.row.col.f32.bf16.bf16.f32 "
                 "{%0,%1,%2,%3}, {%4,%5,%6,%7}, {%8,%9}, {%0,%1,%2,%3};"
                 : "+f"(c[0]), "+f"(c[1]), "+f"(c[2]), "+f"(c[3])
                 : "r"(a[0]), "r"(a[1]), "r"(a[2]), "r"(a[3]), "r"(b0), "r"(b1));
}
__device__ __forceinline__ void split2(float a, float b, uint32_t& hi, uint32_t& lo) {
    __nv_bfloat162 hp = __floats2bfloat162_rn(a, b);
    float ar = a - __bfloat162float(hp.x);
    float br = b - __bfloat162float(hp.y);
    __nv_bfloat162 lp = __floats2bfloat162_rn(ar, br);
    hi = *reinterpret_cast<uint32_t*>(&hp);
    lo = *reinterpret_cast<uint32_t*>(&lp);
}

// ---------------------------------------------------------------------------
// SMEM: two 32KB tile buffers (KHI/KLO/VHI/VLO 8KB each, 64 rows x 128B) +
// 2 mask bufs. Q staging (hi 16KB @0, lo 16KB @16384) spans both buffers
// before the main loop (consumed into registers before tile 0 arrives).
// ---------------------------------------------------------------------------
#define BUFSZ  32768u
#define OKLO   8192u
#define OVHI   16384u
#define OVLO   24576u
#define OMSK   65536u
#define SMEM_BYTES (66048u + 1024u)

// ---------------------------------------------------------------------------
// FA2 attention, mma.sync bf16 hi/lo. CTA = 128 q rows (8 warps x 16 rows),
// 256 threads. Double-buffered cp.async K/V tiles (64 keys).
// ---------------------------------------------------------------------------
__global__ __launch_bounds__(256, 1)
void flash_mma(const __nv_bfloat16* __restrict__ Qhi, const __nv_bfloat16* __restrict__ Qlo,
               const __nv_bfloat16* __restrict__ Khi, const __nv_bfloat16* __restrict__ Klo,
               const __nv_bfloat16* __restrict__ Vhi, const __nv_bfloat16* __restrict__ Vlo,
               const int* __restrict__ mask, float* __restrict__ O)
{
    extern __shared__ char dsm[];
    char* sb = (char*)(((uintptr_t)dsm + 1023) & ~(uintptr_t)1023);
    const uint32_t sbase = smem_u32(sb);

    const int tid  = threadIdx.x;
    const int wid  = tid >> 5;
    const int lane = tid & 31;

    const int b  = blockIdx.y >> 3;
    const int h  = blockIdx.y & 7;
    const int q0 = blockIdx.x * 128;

    const size_t bh_off = (size_t)b * SEQ * DMODEL + h * DK;
    const __nv_bfloat16* Qbh = Qhi + bh_off + (size_t)q0 * DMODEL;
    const __nv_bfloat16* Qbl = Qlo + bh_off + (size_t)q0 * DMODEL;
    const __nv_bfloat16* Kbh = Khi + bh_off;
    const __nv_bfloat16* Kbl = Klo + bh_off;
    const __nv_bfloat16* Vbh = Vhi + bh_off;
    const __nv_bfloat16* Vbl = Vlo + bh_off;
    const int* mb = mask + (size_t)b * SEQ;

    // ---- stage Q (128x64 hi/lo) via cp.async: row = tid>>1, 4 chunks each ----
    {
        const int qrow = tid >> 1;
        const int qc0  = (tid & 1) * 4;
        const __nv_bfloat16* qh_src = Qbh + (size_t)qrow * DMODEL;
        const __nv_bfloat16* ql_src = Qbl + (size_t)qrow * DMODEL;
#pragma unroll
        for (int e = 0; e < 4; e++) {
            int ch = qc0 + e;
            uint32_t so = SWZ((uint32_t)qrow * 128u + (uint32_t)ch * 16u);
            cpa16(sbase + so,          qh_src + ch * 8);
            cpa16(sbase + 16384u + so, ql_src + ch * 8);
        }
        CP_COMMIT();
    }
    CP_WAIT(0);
    __syncthreads();

    // ---- Q fragments: per warp rows wid*16..wid*16+15 ----
    uint32_t qh[4][4], ql[4][4];
    {
        const int r  = wid * 16 + (lane & 15);
        const int cb = (lane >> 4);
#pragma unroll
        for (int ks = 0; ks < 4; ks++) {
            uint32_t off = SWZ((uint32_t)r * 128u + (uint32_t)(ks * 2 + cb) * 16u);
            ldsm_x4(qh[ks], sbase + off);
            ldsm_x4(ql[ks], sbase + 16384u + off);
        }
    }
    __syncthreads();   // Q staging consumed before K/V tile 0 overwrites

    // K/V tile load mapping: 256 threads, row = tid>>2 (0..63), 2 chunks each
    const int row = tid >> 2;
    const int ch0 = (tid & 3) * 2;

    // ---- prologue: prefetch tile 0 into buffer 0 ----
    {
        size_t ro = (size_t)row * DMODEL;
#pragma unroll
        for (int e = 0; e < 2; e++) {
            int ch = ch0 + e;
            uint32_t so = SWZ((uint32_t)row * 128u + (uint32_t)ch * 16u);
            cpa16(sbase + so,        Kbh + ro + ch * 8);
            cpa16(sbase + OKLO + so, Kbl + ro + ch * 8);
            cpa16(sbase + OVHI + so, Vbh + ro + ch * 8);
            cpa16(sbase + OVLO + so, Vbl + ro + ch * 8);
        }
        CP_COMMIT();
        if (tid < 64) ((float*)(sb + OMSK))[tid] = (mb[tid] == 0) ? -1e9f : 0.f;
    }

    float o[8][4];
#pragma unroll
    for (int nb = 0; nb < 8; nb++)
#pragma unroll
        for (int j = 0; j < 4; j++) o[nb][j] = 0.f;
    float m0 = -1e30f, m1 = -1e30f, l0 = 0.f, l1 = 0.f;

    const int nT = SEQ / 64;
    for (int t = 0; t < nT; t++) {
        const uint32_t p  = (uint32_t)(t & 1);
        const uint32_t bb = sbase + p * BUFSZ;
        float* mskp = (float*)(sb + OMSK + p * 256u);

        // prefetch tile t+1 into other buffer
        if (t + 1 < nT) {
            size_t ro = (size_t)((t + 1) * 64 + row) * DMODEL;
            uint32_t ob = sbase + (p ^ 1u) * BUFSZ;
#pragma unroll
            for (int e = 0; e < 2; e++) {
                int ch = ch0 + e;
                uint32_t so = SWZ((uint32_t)row * 128u + (uint32_t)ch * 16u);
                cpa16(ob + so,        Kbh + ro + ch * 8);
                cpa16(ob + OKLO + so, Kbl + ro + ch * 8);
                cpa16(ob + OVHI + so, Vbh + ro + ch * 8);
                cpa16(ob + OVLO + so, Vbl + ro + ch * 8);
            }
            if (tid < 64)
                ((float*)(sb + OMSK + (p ^ 1u) * 256u))[tid] =
                    (mb[(t + 1) * 64 + tid] == 0) ? -1e9f : 0.f;
        }
        CP_COMMIT();
        CP_WAIT(1);
        __syncthreads();   // tile t data + mask visible to all warps

        // ---- S = Q K^T (HH + LH + HL) ----
        float s[8][4];
#pragma unroll
        for (int nb = 0; nb < 8; nb++) {
#pragma unroll
            for (int j = 0; j < 4; j++) s[nb][j] = 0.f;
#pragma unroll
            for (int ks = 0; ks < 4; ks++) {
                const int krow = nb * 8 + (lane & 7);
                const int kch  = ks * 2 + ((lane >> 3) & 1);
                uint32_t off = SWZ((uint32_t)krow * 128u + (uint32_t)kch * 16u);
                uint32_t bh0, bh1, bl0, bl1;
                ldsm_x2(bh0, bh1, bb + off);
                ldsm_x2(bl0, bl1, bb + OKLO + off);
                mma16816(s[nb], qh[ks], bh0, bh1);
                mma16816(s[nb], ql[ks], bh0, bh1);
                mma16816(s[nb], qh[ks], bl0, bl1);
            }
        }

        // ---- online softmax ----
        float rm0 = -1e30f, rm1 = -1e30f;
#pragma unroll
        for (int nb = 0; nb < 8; nb++) {
            float2 mk = *(const float2*)(mskp + nb * 8 + (lane & 3) * 2);
            s[nb][0] = s[nb][0] * 0.125f + mk.x;
            s[nb][1] = s[nb][1] * 0.125f + mk.y;
            s[nb][2] = s[nb][2] * 0.125f + mk.x;
            s[nb][3] = s[nb][3] * 0.125f + mk.y;
            rm0 = fmaxf(rm0, fmaxf(s[nb][0], s[nb][1]));
            rm1 = fmaxf(rm1, fmaxf(s[nb][2], s[nb][3]));
        }
        rm0 = fmaxf(rm0, __shfl_xor_sync(0xffffffffu, rm0, 1));
        rm0 = fmaxf(rm0, __shfl_xor_sync(0xffffffffu, rm0, 2));
        rm1 = fmaxf(rm1, __shfl_xor_sync(0xffffffffu, rm1, 1));
        rm1 = fmaxf(rm1, __shfl_xor_sync(0xffffffffu, rm1, 2));

        const float mn0 = fmaxf(m0, rm0), mn1 = fmaxf(m1, rm1);
        const float a0 = __expf(m0 - mn0), a1 = __expf(m1 - mn1);
        m0 = mn0; m1 = mn1;

        float rs0 = 0.f, rs1 = 0.f;
#pragma unroll
        for (int nb = 0; nb < 8; nb++) {
            s[nb][0] = __expf(s[nb][0] - mn0);
            s[nb][1] = __expf(s[nb][1] - mn0);
            s[nb][2] = __expf(s[nb][2] - mn1);
            s[nb][3] = __expf(s[nb][3] - mn1);
            rs0 += s[nb][0] + s[nb][1];
            rs1 += s[nb][2] + s[nb][3];
        }
        rs0 += __shfl_xor_sync(0xffffffffu, rs0, 1);
        rs0 += __shfl_xor_sync(0xffffffffu, rs0, 2);
        rs1 += __shfl_xor_sync(0xffffffffu, rs1, 1);
        rs1 += __shfl_xor_sync(0xffffffffu, rs1, 2);
        l0 = l0 * a0 + rs0;
        l1 = l1 * a1 + rs1;

#pragma unroll
        for (int nb = 0; nb < 8; nb++) {
            o[nb][0] *= a0; o[nb][1] *= a0;
            o[nb][2] *= a1; o[nb][3] *= a1;
        }

        // ---- P -> bf16 hi/lo fragments ----
        uint32_t ph[8][2], pl[8][2];
#pragma unroll
        for (int nb = 0; nb < 8; nb++) {
            split2(s[nb][0], s[nb][1], ph[nb][0], pl[nb][0]);
            split2(s[nb][2], s[nb][3], ph[nb][1], pl[nb][1]);
        }

        // ---- O += P V (ph*vh + pl*vh + ph*vl) ----
#pragma unroll
        for (int nb = 0; nb < 8; nb++) {
#pragma unroll
            for (int ks = 0; ks < 4; ks++) {
                const int vrow = ks * 16 + (lane & 15);
                uint32_t off = SWZ((uint32_t)vrow * 128u + (uint32_t)nb * 16u);
                uint32_t vh0, vh1, vl0, vl1;
                ldsm_x2t(vh0, vh1, bb + OVHI + off);
                ldsm_x2t(vl0, vl1, bb + OVLO + off);
                uint32_t ah[4] = {ph[2 * ks][0], ph[2 * ks][1], ph[2 * ks + 1][0], ph[2 * ks + 1][1]};
                uint32_t al[4] = {pl[2 * ks][0], pl[2 * ks][1], pl[2 * ks + 1][0], pl[2 * ks + 1][1]};
                mma16816(o[nb], ah, vh0, vh1);
                mma16816(o[nb], al, vh0, vh1);
                mma16816(o[nb], ah, vl0, vl1);
            }
        }
        __syncthreads();   // all warps done with buffer p before refill
    }

    // ---- epilogue ----
    const float i0 = 1.f / l0, i1 = 1.f / l1;
    const int r  = lane >> 2;
    const int cb = (lane & 3) * 2;
    float* Ob = O + ((size_t)b * SEQ + q0 + wid * 16) * DMODEL + h * DK;
#pragma unroll
    for (int nb = 0; nb < 8; nb++) {
        float2 v0 = make_float2(o[nb][0] * i0, o[nb][1] * i0);
        float2 v1 = make_float2(o[nb][2] * i1, o[nb][3] * i1);
        *(float2*)(Ob + (size_t)r * DMODEL + nb * 8 + cb)       = v0;
        *(float2*)(Ob + (size_t)(r + 8) * DMODEL + nb * 8 + cb) = v1;
    }
}

// ---------------------------------------------------------------------------
// fp32 GEMM (C = A @ W^T + b), epilogue writes bf16 hi/lo arrays
// ---------------------------------------------------------------------------
__global__ __launch_bounds__(256)
void gemm_bias_split(const float* __restrict__ A, const float* __restrict__ W,
                     const float* __restrict__ bias,
                     __nv_bfloat16* __restrict__ Chi, __nv_bfloat16* __restrict__ Clo,
                     int M, int N, int K)
{
    __shared__ float As[16][128];
    __shared__ float Ws[16][128];

    const int tid  = threadIdx.x;
    const int brow = blockIdx.y * 128;
    const int bcol = blockIdx.x * 128;
    const int tr   = (tid / 16) * 8;
    const int tc   = (tid % 16) * 8;
    const int lr   = tid / 4;
    const int lc   = (tid % 4) * 4;

    float acc[8][8];
#pragma unroll
    for (int i = 0; i < 8; i++)
#pragma unroll
        for (int j = 0; j < 8; j++) acc[i][j] = 0.f;

    for (int k0 = 0; k0 < K; k0 += 16) {
#pragma unroll
        for (int i = 0; i < 2; i++) {
            int r = lr + i * 64;
            float4 va = *reinterpret_cast<const float4*>(A + (size_t)(brow + r) * K + k0 + lc);
            As[lc + 0][r] = va.x; As[lc + 1][r] = va.y;
            As[lc + 2][r] = va.z; As[lc + 3][r] = va.w;
            float4 vw = *reinterpret_cast<const float4*>(W + (size_t)(bcol + r) * K + k0 + lc);
            Ws[lc + 0][r] = vw.x; Ws[lc + 1][r] = vw.y;
            Ws[lc + 2][r] = vw.z; Ws[lc + 3][r] = vw.w;
        }
        __syncthreads();
#pragma unroll
        for (int k = 0; k < 16; k++) {
            float4 a0 = *reinterpret_cast<const float4*>(&As[k][tr]);
            float4 a1 = *reinterpret_cast<const float4*>(&As[k][tr + 4]);
            float4 b0 = *reinterpret_cast<const float4*>(&Ws[k][tc]);
            float4 b1 = *reinterpret_cast<const float4*>(&Ws[k][tc + 4]);
            float a[8] = {a0.x, a0.y, a0.z, a0.w, a1.x, a1.y, a1.z, a1.w};
            float b[8] = {b0.x, b0.y, b0.z, b0.w, b1.x, b1.y, b1.z, b1.w};
#pragma unroll
            for (int i = 0; i < 8; i++)
#pragma unroll
                for (int j = 0; j < 8; j++)
                    acc[i][j] += a[i] * b[j];
        }
        __syncthreads();
    }

    float4 bv0 = *reinterpret_cast<const float4*>(bias + bcol + tc);
    float4 bv1 = *reinterpret_cast<const float4*>(bias + bcol + tc + 4);
    float bb[8] = {bv0.x, bv0.y, bv0.z, bv0.w, bv1.x, bv1.y, bv1.z, bv1.w};
#pragma unroll
    for (int i = 0; i < 8; i++) {
        uint32_t hv[4], lv[4];
#pragma unroll
        for (int e = 0; e < 4; e++)
            split2(acc[i][2 * e] + bb[2 * e], acc[i][2 * e + 1] + bb[2 * e + 1], hv[e], lv[e]);
        size_t off = (size_t)(brow + tr + i) * N + bcol + tc;
        *reinterpret_cast<uint4*>(Chi + off) = make_uint4(hv[0], hv[1], hv[2], hv[3]);
        *reinterpret_cast<uint4*>(Clo + off) = make_uint4(lv[0], lv[1], lv[2], lv[3]);
    }
}

// ---------------------------------------------------------------------------
// fp32 GEMM with fp32 output (O projection)
// ---------------------------------------------------------------------------
__global__ __launch_bounds__(256)
void gemm_bias_kernel(const float* __restrict__ A, const float* __restrict__ W,
                      const float* __restrict__ bias, float* __restrict__ C,
                      int M, int N, int K)
{
    __shared__ float As[16][128];
    __shared__ float Ws[16][128];

    const int tid  = threadIdx.x;
    const int brow = blockIdx.y * 128;
    const int bcol = blockIdx.x * 128;
    const int tr   = (tid / 16) * 8;
    const int tc   = (tid % 16) * 8;
    const int lr   = tid / 4;
    const int lc   = (tid % 4) * 4;

    float acc[8][8];
#pragma unroll
    for (int i = 0; i < 8; i++)
#pragma unroll
        for (int j = 0; j < 8; j++) acc[i][j] = 0.f;

    for (int k0 = 0; k0 < K; k0 += 16) {
#pragma unroll
        for (int i = 0; i < 2; i++) {
            int r = lr + i * 64;
            float4 va = *reinterpret_cast<const float4*>(A + (size_t)(brow + r) * K + k0 + lc);
            As[lc + 0][r] = va.x; As[lc + 1][r] = va.y;
            As[lc + 2][r] = va.z; As[lc + 3][r] = va.w;
            float4 vw = *reinterpret_cast<const float4*>(W + (size_t)(bcol + r) * K + k0 + lc);
            Ws[lc + 0][r] = vw.x; Ws[lc + 1][r] = vw.y;
            Ws[lc + 2][r] = vw.z; Ws[lc + 3][r] = vw.w;
        }
        __syncthreads();
#pragma unroll
        for (int k = 0; k < 16; k++) {
            float4 a0 = *reinterpret_cast<const float4*>(&As[k][tr]);
            float4 a1 = *reinterpret_cast<const float4*>(&As[k][tr + 4]);
            float4 b0 = *reinterpret_cast<const float4*>(&Ws[k][tc]);
            float4 b1 = *reinterpret_cast<const float4*>(&Ws[k][tc + 4]);
            float a[8] = {a0.x, a0.y, a0.z, a0.w, a1.x, a1.y, a1.z, a1.w};
            float b[8] = {b0.x, b0.y, b0.z, b0.w, b1.x, b1.y, b1.z, b1.w};
#pragma unroll
            for (int i = 0; i < 8; i++)
#pragma unroll
                for (int j = 0; j < 8; j++)
                    acc[i][j] += a[i] * b[j];
        }
        __syncthreads();
    }

    float4 bv0 = *reinterpret_cast<const float4*>(bias + bcol + tc);
    float4 bv1 = *reinterpret_cast<const float4*>(bias + bcol + tc + 4);
    float bb[8] = {bv0.x, bv0.y, bv0.z, bv0.w, bv1.x, bv1.y, bv1.z, bv1.w};
#pragma unroll
    for (int i = 0; i < 8; i++) {
        float4 o0 = make_float4(acc[i][0] + bb[0], acc[i][1] + bb[1],
                                acc[i][2] + bb[2], acc[i][3] + bb[3]);
        float4 o1 = make_float4(acc[i][4] + bb[4], acc[i][5] + bb[5],
                                acc[i][6] + bb[6], acc[i][7] + bb[7]);
        float* crow = C + (size_t)(brow + tr + i) * N + bcol + tc;
        *reinterpret_cast<float4*>(crow)     = o0;
        *reinterpret_cast<float4*>(crow + 4) = o1;
    }
}

// ---------------------------------------------------------------------------
extern "C" void kernel_launch(void* const* d_in, const int* in_sizes, int n_in,
                              void* d_out, int out_size)
{
    const float* q    = (const float*)d_in[0];
    const float* k    = (const float*)d_in[1];
    const float* v    = (const float*)d_in[2];
    const int*   mask = (const int*)  d_in[3];
    const float* Wq   = (const float*)d_in[4];
    const float* bq   = (const float*)d_in[5];
    const float* Wk   = (const float*)d_in[6];
    const float* bk   = (const float*)d_in[7];
    const float* Wv   = (const float*)d_in[8];
    const float* bv   = (const float*)d_in[9];
    const float* Wo   = (const float*)d_in[10];
    const float* bo   = (const float*)d_in[11];

    const int S = SEQ, D = DMODEL;
    const int B = in_sizes[0] / (S * D);
    const int M = B * S;

    __nv_bfloat16 *gQh, *gQl, *gKh, *gKl, *gVh, *gVl;
    float* gC;
    cudaGetSymbolAddress((void**)&gQh, g_Qhi);
    cudaGetSymbolAddress((void**)&gQl, g_Qlo);
    cudaGetSymbolAddress((void**)&gKh, g_Khi);
    cudaGetSymbolAddress((void**)&gKl, g_Klo);
    cudaGetSymbolAddress((void**)&gVh, g_Vhi);
    cudaGetSymbolAddress((void**)&gVl, g_Vlo);
    cudaGetSymbolAddress((void**)&gC,  g_C);

    dim3 ggrid(D / 128, M / 128);
    gemm_bias_split<<<ggrid, 256>>>(q, Wq, bq, gQh, gQl, M, D, D);
    gemm_bias_split<<<ggrid, 256>>>(k, Wk, bk, gKh, gKl, M, D, D);
    gemm_bias_split<<<ggrid, 256>>>(v, Wv, bv, gVh, gVl, M, D, D);

    cudaFuncSetAttribute(flash_mma, cudaFuncAttributeMaxDynamicSharedMemorySize, SMEM_BYTES);
    flash_mma<<<dim3(S / 128, B * NHEAD), 256, SMEM_BYTES>>>(gQh, gQl, gKh, gKl, gVh, gVl, mask, gC);

    gemm_bias_kernel<<<ggrid, 256>>>(gC, Wo, bo, (float*)d_out, M, D, D);
}

// round 6
// speedup vs baseline: 1.9766x; 1.2320x over previous
#include <cuda_runtime.h>
#include <cuda_bf16.h>
#include <cstdint>
#include <cstddef>

#define SEQ    4096
#define DMODEL 512
#define NHEAD  8
#define DK     64

// ---------------------------------------------------------------------------
// Scratch (device globals — no allocation in kernel_launch)
// ---------------------------------------------------------------------------
__device__ __nv_bfloat16 g_qin_h[2 * SEQ * DMODEL], g_qin_l[2 * SEQ * DMODEL];
__device__ __nv_bfloat16 g_kin_h[2 * SEQ * DMODEL], g_kin_l[2 * SEQ * DMODEL];
__device__ __nv_bfloat16 g_vin_h[2 * SEQ * DMODEL], g_vin_l[2 * SEQ * DMODEL];
__device__ __nv_bfloat16 g_Qhi[2 * SEQ * DMODEL], g_Qlo[2 * SEQ * DMODEL];
__device__ __nv_bfloat16 g_Khi[2 * SEQ * DMODEL], g_Klo[2 * SEQ * DMODEL];
__device__ __nv_bfloat16 g_Vhi[2 * SEQ * DMODEL], g_Vlo[2 * SEQ * DMODEL];
__device__ __nv_bfloat16 g_Chi[2 * SEQ * DMODEL], g_Clo[2 * SEQ * DMODEL];
__device__ __nv_bfloat16 g_Wq_h[DMODEL * DMODEL], g_Wq_l[DMODEL * DMODEL];
__device__ __nv_bfloat16 g_Wk_h[DMODEL * DMODEL], g_Wk_l[DMODEL * DMODEL];
__device__ __nv_bfloat16 g_Wv_h[DMODEL * DMODEL], g_Wv_l[DMODEL * DMODEL];
__device__ __nv_bfloat16 g_Wo_h[DMODEL * DMODEL], g_Wo_l[DMODEL * DMODEL];

// ---------------------------------------------------------------------------
// helpers
// ---------------------------------------------------------------------------
#define SWZ(o) ((o) ^ (((o) >> 3) & 0x70))

__device__ __forceinline__ uint32_t smem_u32(const void* p) {
    uint32_t a;
    asm("{ .reg .u64 t; cvta.to.shared.u64 t, %1; cvt.u32.u64 %0, t; }" : "=r"(a) : "l"(p));
    return a;
}
__device__ __forceinline__ void cpa16(uint32_t dst, const void* src) {
    asm volatile("cp.async.cg.shared.global [%0], [%1], 16;" :: "r"(dst), "l"(src) : "memory");
}
#define CP_COMMIT() asm volatile("cp.async.commit_group;" ::: "memory")
#define CP_WAIT(n)  asm volatile("cp.async.wait_group %0;" :: "n"(n) : "memory")

__device__ __forceinline__ void ldsm_x4(uint32_t* r, uint32_t addr) {
    asm volatile("ldmatrix.sync.aligned.m8n8.x4.shared.b16 {%0,%1,%2,%3}, [%4];"
                 : "=r"(r[0]), "=r"(r[1]), "=r"(r[2]), "=r"(r[3]) : "r"(addr));
}
__device__ __forceinline__ void ldsm_x2(uint32_t& r0, uint32_t& r1, uint32_t addr) {
    asm volatile("ldmatrix.sync.aligned.m8n8.x2.shared.b16 {%0,%1}, [%2];"
                 : "=r"(r0), "=r"(r1) : "r"(addr));
}
__device__ __forceinline__ void ldsm_x2t(uint32_t& r0, uint32_t& r1, uint32_t addr) {
    asm volatile("ldmatrix.sync.aligned.m8n8.x2.trans.shared.b16 {%0,%1}, [%2];"
                 : "=r"(r0), "=r"(r1) : "r"(addr));
}
__device__ __forceinline__ void mma16816(float* c, const uint32_t* a, uint32_t b0, uint32_t b1) {
    asm volatile("mma.sync.aligned.m16n8k16.row.col.f32.bf16.bf16.f32 "
                 "{%0,%1,%2,%3}, {%4,%5,%6,%7}, {%8,%9}, {%0,%1,%2,%3};"
                 : "+f"(c[0]), "+f"(c[1]), "+f"(c[2]), "+f"(c[3])
                 : "r"(a[0]), "r"(a[1]), "r"(a[2]), "r"(a[3]), "r"(b0), "r"(b1));
}
__device__ __forceinline__ void split2(float a, float b, uint32_t& hi, uint32_t& lo) {
    __nv_bfloat162 hp = __floats2bfloat162_rn(a, b);
    float ar = a - __bfloat162float(hp.x);
    float br = b - __bfloat162float(hp.y);
    __nv_bfloat162 lp = __floats2bfloat162_rn(ar, br);
    hi = *reinterpret_cast<uint32_t*>(&hp);
    lo = *reinterpret_cast<uint32_t*>(&lp);
}

// ---------------------------------------------------------------------------
// elementwise fp32 -> bf16 hi/lo
// ---------------------------------------------------------------------------
__global__ __launch_bounds__(256)
void convert_split(const float* __restrict__ X, __nv_bfloat16* __restrict__ hi,
                   __nv_bfloat16* __restrict__ lo, int n4)
{
    int i = blockIdx.x * blockDim.x + threadIdx.x;
    if (i >= n4) return;
    float4 v = *reinterpret_cast<const float4*>(X + (size_t)i * 4);
    uint32_t h0, l0, h1, l1;
    split2(v.x, v.y, h0, l0);
    split2(v.z, v.w, h1, l1);
    *reinterpret_cast<uint2*>(hi + (size_t)i * 4) = make_uint2(h0, h1);
    *reinterpret_cast<uint2*>(lo + (size_t)i * 4) = make_uint2(l0, l1);
}

// ---------------------------------------------------------------------------
// Tensor-core GEMM: C[M,N] = Ahi/lo[M,K] @ (Whi/lo[N,K])^T + bias
// 128x128 tile, K-step 64, 8 warps (2x4), double-buffered cp.async.
// ---------------------------------------------------------------------------
#define GA_HI 0u
#define GA_LO 16384u
#define GW_HI 32768u
#define GW_LO 49152u
#define GBUF  65536u
#define GSMEM (131072u + 1024u)

template<bool SPLIT>
__global__ __launch_bounds__(256, 1)
void gemm_mma(const __nv_bfloat16* __restrict__ Ahi, const __nv_bfloat16* __restrict__ Alo,
              const __nv_bfloat16* __restrict__ Whi, const __nv_bfloat16* __restrict__ Wlo,
              const float* __restrict__ bias,
              float* __restrict__ Cf,
              __nv_bfloat16* __restrict__ Chi, __nv_bfloat16* __restrict__ Clo,
              int M, int N, int K)
{
    extern __shared__ char dsm[];
    char* sb = (char*)(((uintptr_t)dsm + 1023) & ~(uintptr_t)1023);
    const uint32_t sbase = smem_u32(sb);

    const int tid  = threadIdx.x;
    const int wid  = tid >> 5;
    const int lane = tid & 31;
    const int wm   = wid & 1;      // 0..1 -> 64 rows each
    const int wn   = wid >> 1;     // 0..3 -> 32 cols each

    const int brow = blockIdx.y * 128;
    const int bcol = blockIdx.x * 128;

    const int row = tid >> 1;           // 0..127
    const int ch0 = (tid & 1) * 4;      // 4 chunks of 16B

    const __nv_bfloat16* a_h = Ahi + (size_t)(brow + row) * K;
    const __nv_bfloat16* a_l = Alo + (size_t)(brow + row) * K;
    const __nv_bfloat16* w_h = Whi + (size_t)(bcol + row) * K;
    const __nv_bfloat16* w_l = Wlo + (size_t)(bcol + row) * K;
    const uint32_t so_base = (uint32_t)row * 128u;

    // prologue: tile 0 into buffer 0
    {
#pragma unroll
        for (int e = 0; e < 4; e++) {
            int ch = ch0 + e;
            uint32_t so = SWZ(so_base + (uint32_t)ch * 16u);
            cpa16(sbase + GA_HI + so, a_h + ch * 8);
            cpa16(sbase + GA_LO + so, a_l + ch * 8);
            cpa16(sbase + GW_HI + so, w_h + ch * 8);
            cpa16(sbase + GW_LO + so, w_l + ch * 8);
        }
        CP_COMMIT();
    }

    float acc[4][4][4];
#pragma unroll
    for (int i = 0; i < 4; i++)
#pragma unroll
        for (int j = 0; j < 4; j++)
#pragma unroll
            for (int e = 0; e < 4; e++) acc[i][j][e] = 0.f;

    const int nKT = K / 64;
    for (int kt = 0; kt < nKT; kt++) {
        const uint32_t p  = (uint32_t)(kt & 1);
        const uint32_t bb = sbase + p * GBUF;

        if (kt + 1 < nKT) {
            const int k1 = (kt + 1) * 64;
            uint32_t ob = sbase + (p ^ 1u) * GBUF;
#pragma unroll
            for (int e = 0; e < 4; e++) {
                int ch = ch0 + e;
                uint32_t so = SWZ(so_base + (uint32_t)ch * 16u);
                cpa16(ob + GA_HI + so, a_h + k1 + ch * 8);
                cpa16(ob + GA_LO + so, a_l + k1 + ch * 8);
                cpa16(ob + GW_HI + so, w_h + k1 + ch * 8);
                cpa16(ob + GW_LO + so, w_l + k1 + ch * 8);
            }
        }
        CP_COMMIT();
        CP_WAIT(1);
        __syncthreads();

#pragma unroll
        for (int ks = 0; ks < 4; ks++) {
            uint32_t ah[4][4], al[4][4];
            const int cb = lane >> 4;
#pragma unroll
            for (int i = 0; i < 4; i++) {
                int r = wm * 64 + i * 16 + (lane & 15);
                uint32_t off = SWZ((uint32_t)r * 128u + (uint32_t)(ks * 2 + cb) * 16u);
                ldsm_x4(ah[i], bb + GA_HI + off);
                ldsm_x4(al[i], bb + GA_LO + off);
            }
            uint32_t bh[4][2], bl[4][2];
#pragma unroll
            for (int j = 0; j < 4; j++) {
                int wr = wn * 32 + j * 8 + (lane & 7);
                int ch = ks * 2 + ((lane >> 3) & 1);
                uint32_t off = SWZ((uint32_t)wr * 128u + (uint32_t)ch * 16u);
                ldsm_x2(bh[j][0], bh[j][1], bb + GW_HI + off);
                ldsm_x2(bl[j][0], bl[j][1], bb + GW_LO + off);
            }
#pragma unroll
            for (int i = 0; i < 4; i++)
#pragma unroll
                for (int j = 0; j < 4; j++) {
                    mma16816(acc[i][j], ah[i], bh[j][0], bh[j][1]);
                    mma16816(acc[i][j], al[i], bh[j][0], bh[j][1]);
                    mma16816(acc[i][j], ah[i], bl[j][0], bl[j][1]);
                }
        }
        __syncthreads();
    }

    // epilogue
#pragma unroll
    for (int i = 0; i < 4; i++) {
        const int gr0 = brow + wm * 64 + i * 16 + (lane >> 2);
        const int gr1 = gr0 + 8;
#pragma unroll
        for (int j = 0; j < 4; j++) {
            const int gc = bcol + wn * 32 + j * 8 + (lane & 3) * 2;
            float b0 = bias[gc], b1 = bias[gc + 1];
            float v0 = acc[i][j][0] + b0, v1 = acc[i][j][1] + b1;
            float v2 = acc[i][j][2] + b0, v3 = acc[i][j][3] + b1;
            if (SPLIT) {
                uint32_t h, l;
                split2(v0, v1, h, l);
                *reinterpret_cast<uint32_t*>(Chi + (size_t)gr0 * N + gc) = h;
                *reinterpret_cast<uint32_t*>(Clo + (size_t)gr0 * N + gc) = l;
                split2(v2, v3, h, l);
                *reinterpret_cast<uint32_t*>(Chi + (size_t)gr1 * N + gc) = h;
                *reinterpret_cast<uint32_t*>(Clo + (size_t)gr1 * N + gc) = l;
            } else {
                *reinterpret_cast<float2*>(Cf + (size_t)gr0 * N + gc) = make_float2(v0, v1);
                *reinterpret_cast<float2*>(Cf + (size_t)gr1 * N + gc) = make_float2(v2, v3);
            }
        }
    }
}

// ---------------------------------------------------------------------------
// SMEM for flash: two 32KB K/V buffers + masks; Q staging spans both.
// ---------------------------------------------------------------------------
#define BUFSZ  32768u
#define OKLO   8192u
#define OVHI   16384u
#define OVLO   24576u
#define OMSK   65536u
#define SMEM_BYTES (66048u + 1024u)

// ---------------------------------------------------------------------------
// FA2 attention, mma.sync bf16 hi/lo. CTA = 128 q rows (8 warps), 256 thr.
// Writes ctx as bf16 hi/lo (consumed by O-proj tensor GEMM).
// ---------------------------------------------------------------------------
__global__ __launch_bounds__(256, 1)
void flash_mma(const __nv_bfloat16* __restrict__ Qhi, const __nv_bfloat16* __restrict__ Qlo,
               const __nv_bfloat16* __restrict__ Khi, const __nv_bfloat16* __restrict__ Klo,
               const __nv_bfloat16* __restrict__ Vhi, const __nv_bfloat16* __restrict__ Vlo,
               const int* __restrict__ mask,
               __nv_bfloat16* __restrict__ Chi, __nv_bfloat16* __restrict__ Clo)
{
    extern __shared__ char dsm[];
    char* sb = (char*)(((uintptr_t)dsm + 1023) & ~(uintptr_t)1023);
    const uint32_t sbase = smem_u32(sb);

    const int tid  = threadIdx.x;
    const int wid  = tid >> 5;
    const int lane = tid & 31;

    const int b  = blockIdx.y >> 3;
    const int h  = blockIdx.y & 7;
    const int q0 = blockIdx.x * 128;

    const size_t bh_off = (size_t)b * SEQ * DMODEL + h * DK;
    const __nv_bfloat16* Qbh = Qhi + bh_off + (size_t)q0 * DMODEL;
    const __nv_bfloat16* Qbl = Qlo + bh_off + (size_t)q0 * DMODEL;
    const __nv_bfloat16* Kbh = Khi + bh_off;
    const __nv_bfloat16* Kbl = Klo + bh_off;
    const __nv_bfloat16* Vbh = Vhi + bh_off;
    const __nv_bfloat16* Vbl = Vlo + bh_off;
    const int* mb = mask + (size_t)b * SEQ;

    // stage Q (128x64 hi/lo)
    {
        const int qrow = tid >> 1;
        const int qc0  = (tid & 1) * 4;
        const __nv_bfloat16* qh_src = Qbh + (size_t)qrow * DMODEL;
        const __nv_bfloat16* ql_src = Qbl + (size_t)qrow * DMODEL;
#pragma unroll
        for (int e = 0; e < 4; e++) {
            int ch = qc0 + e;
            uint32_t so = SWZ((uint32_t)qrow * 128u + (uint32_t)ch * 16u);
            cpa16(sbase + so,          qh_src + ch * 8);
            cpa16(sbase + 16384u + so, ql_src + ch * 8);
        }
        CP_COMMIT();
    }
    CP_WAIT(0);
    __syncthreads();

    uint32_t qh[4][4], ql[4][4];
    {
        const int r  = wid * 16 + (lane & 15);
        const int cb = (lane >> 4);
#pragma unroll
        for (int ks = 0; ks < 4; ks++) {
            uint32_t off = SWZ((uint32_t)r * 128u + (uint32_t)(ks * 2 + cb) * 16u);
            ldsm_x4(qh[ks], sbase + off);
            ldsm_x4(ql[ks], sbase + 16384u + off);
        }
    }
    __syncthreads();

    const int row = tid >> 2;
    const int ch0 = (tid & 3) * 2;

    {
        size_t ro = (size_t)row * DMODEL;
#pragma unroll
        for (int e = 0; e < 2; e++) {
            int ch = ch0 + e;
            uint32_t so = SWZ((uint32_t)row * 128u + (uint32_t)ch * 16u);
            cpa16(sbase + so,        Kbh + ro + ch * 8);
            cpa16(sbase + OKLO + so, Kbl + ro + ch * 8);
            cpa16(sbase + OVHI + so, Vbh + ro + ch * 8);
            cpa16(sbase + OVLO + so, Vbl + ro + ch * 8);
        }
        CP_COMMIT();
        if (tid < 64) ((float*)(sb + OMSK))[tid] = (mb[tid] == 0) ? -1e9f : 0.f;
    }

    float o[8][4];
#pragma unroll
    for (int nb = 0; nb < 8; nb++)
#pragma unroll
        for (int j = 0; j < 4; j++) o[nb][j] = 0.f;
    float m0 = -1e30f, m1 = -1e30f, l0 = 0.f, l1 = 0.f;

    const int nT = SEQ / 64;
    for (int t = 0; t < nT; t++) {
        const uint32_t p  = (uint32_t)(t & 1);
        const uint32_t bb = sbase + p * BUFSZ;
        float* mskp = (float*)(sb + OMSK + p * 256u);

        if (t + 1 < nT) {
            size_t ro = (size_t)((t + 1) * 64 + row) * DMODEL;
            uint32_t ob = sbase + (p ^ 1u) * BUFSZ;
#pragma unroll
            for (int e = 0; e < 2; e++) {
                int ch = ch0 + e;
                uint32_t so = SWZ((uint32_t)row * 128u + (uint32_t)ch * 16u);
                cpa16(ob + so,        Kbh + ro + ch * 8);
                cpa16(ob + OKLO + so, Kbl + ro + ch * 8);
                cpa16(ob + OVHI + so, Vbh + ro + ch * 8);
                cpa16(ob + OVLO + so, Vbl + ro + ch * 8);
            }
            if (tid < 64)
                ((float*)(sb + OMSK + (p ^ 1u) * 256u))[tid] =
                    (mb[(t + 1) * 64 + tid] == 0) ? -1e9f : 0.f;
        }
        CP_COMMIT();
        CP_WAIT(1);
        __syncthreads();

        // S = Q K^T
        float s[8][4];
#pragma unroll
        for (int nb = 0; nb < 8; nb++) {
#pragma unroll
            for (int j = 0; j < 4; j++) s[nb][j] = 0.f;
#pragma unroll
            for (int ks = 0; ks < 4; ks++) {
                const int krow = nb * 8 + (lane & 7);
                const int kch  = ks * 2 + ((lane >> 3) & 1);
                uint32_t off = SWZ((uint32_t)krow * 128u + (uint32_t)kch * 16u);
                uint32_t bh0, bh1, bl0, bl1;
                ldsm_x2(bh0, bh1, bb + off);
                ldsm_x2(bl0, bl1, bb + OKLO + off);
                mma16816(s[nb], qh[ks], bh0, bh1);
                mma16816(s[nb], ql[ks], bh0, bh1);
                mma16816(s[nb], qh[ks], bl0, bl1);
            }
        }

        // online softmax
        float rm0 = -1e30f, rm1 = -1e30f;
#pragma unroll
        for (int nb = 0; nb < 8; nb++) {
            float2 mk = *(const float2*)(mskp + nb * 8 + (lane & 3) * 2);
            s[nb][0] = s[nb][0] * 0.125f + mk.x;
            s[nb][1] = s[nb][1] * 0.125f + mk.y;
            s[nb][2] = s[nb][2] * 0.125f + mk.x;
            s[nb][3] = s[nb][3] * 0.125f + mk.y;
            rm0 = fmaxf(rm0, fmaxf(s[nb][0], s[nb][1]));
            rm1 = fmaxf(rm1, fmaxf(s[nb][2], s[nb][3]));
        }
        rm0 = fmaxf(rm0, __shfl_xor_sync(0xffffffffu, rm0, 1));
        rm0 = fmaxf(rm0, __shfl_xor_sync(0xffffffffu, rm0, 2));
        rm1 = fmaxf(rm1, __shfl_xor_sync(0xffffffffu, rm1, 1));
        rm1 = fmaxf(rm1, __shfl_xor_sync(0xffffffffu, rm1, 2));

        const float mn0 = fmaxf(m0, rm0), mn1 = fmaxf(m1, rm1);
        const float a0 = __expf(m0 - mn0), a1 = __expf(m1 - mn1);
        m0 = mn0; m1 = mn1;

        float rs0 = 0.f, rs1 = 0.f;
#pragma unroll
        for (int nb = 0; nb < 8; nb++) {
            s[nb][0] = __expf(s[nb][0] - mn0);
            s[nb][1] = __expf(s[nb][1] - mn0);
            s[nb][2] = __expf(s[nb][2] - mn1);
            s[nb][3] = __expf(s[nb][3] - mn1);
            rs0 += s[nb][0] + s[nb][1];
            rs1 += s[nb][2] + s[nb][3];
        }
        rs0 += __shfl_xor_sync(0xffffffffu, rs0, 1);
        rs0 += __shfl_xor_sync(0xffffffffu, rs0, 2);
        rs1 += __shfl_xor_sync(0xffffffffu, rs1, 1);
        rs1 += __shfl_xor_sync(0xffffffffu, rs1, 2);
        l0 = l0 * a0 + rs0;
        l1 = l1 * a1 + rs1;

#pragma unroll
        for (int nb = 0; nb < 8; nb++) {
            o[nb][0] *= a0; o[nb][1] *= a0;
            o[nb][2] *= a1; o[nb][3] *= a1;
        }

        uint32_t ph[8][2], pl[8][2];
#pragma unroll
        for (int nb = 0; nb < 8; nb++) {
            split2(s[nb][0], s[nb][1], ph[nb][0], pl[nb][0]);
            split2(s[nb][2], s[nb][3], ph[nb][1], pl[nb][1]);
        }

        // O += P V
#pragma unroll
        for (int nb = 0; nb < 8; nb++) {
#pragma unroll
            for (int ks = 0; ks < 4; ks++) {
                const int vrow = ks * 16 + (lane & 15);
                uint32_t off = SWZ((uint32_t)vrow * 128u + (uint32_t)nb * 16u);
                uint32_t vh0, vh1, vl0, vl1;
                ldsm_x2t(vh0, vh1, bb + OVHI + off);
                ldsm_x2t(vl0, vl1, bb + OVLO + off);
                uint32_t ah[4] = {ph[2 * ks][0], ph[2 * ks][1], ph[2 * ks + 1][0], ph[2 * ks + 1][1]};
                uint32_t al[4] = {pl[2 * ks][0], pl[2 * ks][1], pl[2 * ks + 1][0], pl[2 * ks + 1][1]};
                mma16816(o[nb], ah, vh0, vh1);
                mma16816(o[nb], al, vh0, vh1);
                mma16816(o[nb], ah, vl0, vl1);
            }
        }
        __syncthreads();
    }

    // epilogue: write ctx hi/lo bf16
    const float i0 = 1.f / l0, i1 = 1.f / l1;
    const int r  = lane >> 2;
    const int cb = (lane & 3) * 2;
    const size_t ob0 = ((size_t)b * SEQ + q0 + wid * 16) * DMODEL + h * DK;
#pragma unroll
    for (int nb = 0; nb < 8; nb++) {
        uint32_t hh, ll;
        size_t off0 = ob0 + (size_t)r * DMODEL + nb * 8 + cb;
        split2(o[nb][0] * i0, o[nb][1] * i0, hh, ll);
        *reinterpret_cast<uint32_t*>(Chi + off0) = hh;
        *reinterpret_cast<uint32_t*>(Clo + off0) = ll;
        size_t off1 = ob0 + (size_t)(r + 8) * DMODEL + nb * 8 + cb;
        split2(o[nb][2] * i1, o[nb][3] * i1, hh, ll);
        *reinterpret_cast<uint32_t*>(Chi + off1) = hh;
        *reinterpret_cast<uint32_t*>(Clo + off1) = ll;
    }
}

// ---------------------------------------------------------------------------
extern "C" void kernel_launch(void* const* d_in, const int* in_sizes, int n_in,
                              void* d_out, int out_size)
{
    const float* q    = (const float*)d_in[0];
    const float* k    = (const float*)d_in[1];
    const float* v    = (const float*)d_in[2];
    const int*   mask = (const int*)  d_in[3];
    const float* Wq   = (const float*)d_in[4];
    const float* bq   = (const float*)d_in[5];
    const float* Wk   = (const float*)d_in[6];
    const float* bk   = (const float*)d_in[7];
    const float* Wv   = (const float*)d_in[8];
    const float* bv   = (const float*)d_in[9];
    const float* Wo   = (const float*)d_in[10];
    const float* bo   = (const float*)d_in[11];

    const int S = SEQ, D = DMODEL;
    const int B = in_sizes[0] / (S * D);
    const int M = B * S;

    __nv_bfloat16 *qin_h, *qin_l, *kin_h, *kin_l, *vin_h, *vin_l;
    __nv_bfloat16 *Qh, *Ql, *Kh, *Kl, *Vh, *Vl, *Ch, *Cl;
    __nv_bfloat16 *Wqh, *Wql, *Wkh, *Wkl, *Wvh, *Wvl, *Woh, *Wol;
    cudaGetSymbolAddress((void**)&qin_h, g_qin_h); cudaGetSymbolAddress((void**)&qin_l, g_qin_l);
    cudaGetSymbolAddress((void**)&kin_h, g_kin_h); cudaGetSymbolAddress((void**)&kin_l, g_kin_l);
    cudaGetSymbolAddress((void**)&vin_h, g_vin_h); cudaGetSymbolAddress((void**)&vin_l, g_vin_l);
    cudaGetSymbolAddress((void**)&Qh, g_Qhi); cudaGetSymbolAddress((void**)&Ql, g_Qlo);
    cudaGetSymbolAddress((void**)&Kh, g_Khi); cudaGetSymbolAddress((void**)&Kl, g_Klo);
    cudaGetSymbolAddress((void**)&Vh, g_Vhi); cudaGetSymbolAddress((void**)&Vl, g_Vlo);
    cudaGetSymbolAddress((void**)&Ch, g_Chi); cudaGetSymbolAddress((void**)&Cl, g_Clo);
    cudaGetSymbolAddress((void**)&Wqh, g_Wq_h); cudaGetSymbolAddress((void**)&Wql, g_Wq_l);
    cudaGetSymbolAddress((void**)&Wkh, g_Wk_h); cudaGetSymbolAddress((void**)&Wkl, g_Wk_l);
    cudaGetSymbolAddress((void**)&Wvh, g_Wv_h); cudaGetSymbolAddress((void**)&Wvl, g_Wv_l);
    cudaGetSymbolAddress((void**)&Woh, g_Wo_h); cudaGetSymbolAddress((void**)&Wol, g_Wo_l);

    // conversions
    const int nIn4 = (M * D) / 4, nW4 = (D * D) / 4;
    convert_split<<<(nIn4 + 255) / 256, 256>>>(q, qin_h, qin_l, nIn4);
    convert_split<<<(nIn4 + 255) / 256, 256>>>(k, kin_h, kin_l, nIn4);
    convert_split<<<(nIn4 + 255) / 256, 256>>>(v, vin_h, vin_l, nIn4);
    convert_split<<<(nW4 + 255) / 256, 256>>>(Wq, Wqh, Wql, nW4);
    convert_split<<<(nW4 + 255) / 256, 256>>>(Wk, Wkh, Wkl, nW4);
    convert_split<<<(nW4 + 255) / 256, 256>>>(Wv, Wvh, Wvl, nW4);
    convert_split<<<(nW4 + 255) / 256, 256>>>(Wo, Woh, Wol, nW4);

    // projections (tensor GEMM, split output)
    cudaFuncSetAttribute(gemm_mma<true>,  cudaFuncAttributeMaxDynamicSharedMemorySize, GSMEM);
    cudaFuncSetAttribute(gemm_mma<false>, cudaFuncAttributeMaxDynamicSharedMemorySize, GSMEM);
    dim3 ggrid(D / 128, M / 128);
    gemm_mma<true><<<ggrid, 256, GSMEM>>>(qin_h, qin_l, Wqh, Wql, bq, nullptr, Qh, Ql, M, D, D);
    gemm_mma<true><<<ggrid, 256, GSMEM>>>(kin_h, kin_l, Wkh, Wkl, bk, nullptr, Kh, Kl, M, D, D);
    gemm_mma<true><<<ggrid, 256, GSMEM>>>(vin_h, vin_l, Wvh, Wvl, bv, nullptr, Vh, Vl, M, D, D);

    // attention
    cudaFuncSetAttribute(flash_mma, cudaFuncAttributeMaxDynamicSharedMemorySize, SMEM_BYTES);
    flash_mma<<<dim3(S / 128, B * NHEAD), 256, SMEM_BYTES>>>(Qh, Ql, Kh, Kl, Vh, Vl, mask, Ch, Cl);

    // output projection (fp32 out)
    gemm_mma<false><<<ggrid, 256, GSMEM>>>(Ch, Cl, Woh, Wol, bo, (float*)d_out, nullptr, nullptr, M, D, D);
}